// round 15
// baseline (speedup 1.0000x reference)
#include <cuda_runtime.h>
#include <cuda_bf16.h>
#include <cstdint>

#define S_LEN 2048
#define D_DIM 1024
#define BATCH 4
#define MTOT  (BATCH * S_LEN)   // 8192

typedef __nv_bfloat16 bf16;

// ============================ device scratch ================================
__device__ bf16  g_xh [(size_t)MTOT * D_DIM];
__device__ bf16  g_xl [(size_t)MTOT * D_DIM];
__device__ bf16  g_wqh[(size_t)D_DIM * D_DIM];   // Wq digits (native layout)
__device__ bf16  g_wql[(size_t)D_DIM * D_DIM];
__device__ bf16  g_wkh[(size_t)D_DIM * D_DIM];   // Wk digits (native layout)
__device__ bf16  g_wkl[(size_t)D_DIM * D_DIM];
__device__ bf16  g_wvth[(size_t)D_DIM * D_DIM];  // Wv^T digits
__device__ bf16  g_wvtl[(size_t)D_DIM * D_DIM];
__device__ bf16  g_mh [(size_t)D_DIM * D_DIM];   // M' = Wk Wq^T digits
__device__ bf16  g_ml [(size_t)D_DIM * D_DIM];
__device__ bf16  g_th [(size_t)MTOT * D_DIM];    // T = x M'^T digits
__device__ bf16  g_tl [(size_t)MTOT * D_DIM];
__device__ bf16  g_vth[(size_t)BATCH * D_DIM * S_LEN];  // V^T digits per batch
__device__ bf16  g_vtl[(size_t)BATCH * D_DIM * S_LEN];
__device__ float g_sc [(size_t)BATCH * S_LEN * S_LEN];
__device__ bf16  g_wh [(size_t)BATCH * S_LEN * S_LEN];
__device__ bf16  g_wl [(size_t)BATCH * S_LEN * S_LEN];

// ============================ PTX helpers ===================================
__device__ __forceinline__ uint32_t smem_u32(const void* p) {
    uint32_t a;
    asm("{ .reg .u64 t; cvta.to.shared.u64 t, %1; cvt.u32.u64 %0, t; }" : "=r"(a) : "l"(p));
    return a;
}
__device__ __forceinline__ void cp16(uint32_t s, const void* g) {
    asm volatile("cp.async.cg.shared.global [%0], [%1], 16;" :: "r"(s), "l"(g) : "memory");
}
#define CP_COMMIT() asm volatile("cp.async.commit_group;" ::: "memory")
#define CP_WAIT(n)  asm volatile("cp.async.wait_group %0;" :: "n"(n) : "memory")

__device__ __forceinline__ void ldm4(uint32_t r[4], uint32_t a) {
    asm volatile("ldmatrix.sync.aligned.m8n8.x4.shared.b16 {%0,%1,%2,%3}, [%4];"
                 : "=r"(r[0]), "=r"(r[1]), "=r"(r[2]), "=r"(r[3]) : "r"(a));
}
__device__ __forceinline__ void mma16816(float c[4], const uint32_t a[4], const uint32_t b[2]) {
    asm volatile("mma.sync.aligned.m16n8k16.row.col.f32.bf16.bf16.f32 "
                 "{%0,%1,%2,%3}, {%4,%5,%6,%7}, {%8,%9}, {%0,%1,%2,%3};"
                 : "+f"(c[0]), "+f"(c[1]), "+f"(c[2]), "+f"(c[3])
                 : "r"(a[0]), "r"(a[1]), "r"(a[2]), "r"(a[3]), "r"(b[0]), "r"(b[1]));
}

// fast exp on fma/alu pipes (no MUFU). Valid for x in [-80, 0.5]; rel err ~5e-8.
__device__ __forceinline__ float fexp(float x) {
    x = fmaxf(x, -80.0f);                       // underflow guard for exponent add
    const float MAGIC = 12582912.0f;            // 1.5 * 2^23
    float t = fmaf(x, 1.4426950408889634f, MAGIC);
    int   ni = __float_as_int(t) - 0x4B400000;  // integer n
    float n = t - MAGIC;
    float r = fmaf(n, -0.6931471824645996f, x); // x - n*ln2_hi
    r = fmaf(n, 1.9046542121259336e-9f, r);     // - n*ln2_lo correction
    float p = 1.3888889e-3f;                    // 1/720
    p = fmaf(p, r, 8.3333333e-3f);              // 1/120
    p = fmaf(p, r, 4.1666667e-2f);              // 1/24
    p = fmaf(p, r, 1.6666667e-1f);              // 1/6
    p = fmaf(p, r, 0.5f);
    p = fmaf(p, r, 1.0f);
    p = fmaf(p, r, 1.0f);
    return __int_as_float(__float_as_int(p) + (ni << 23));
}

// ====================== split-bf16 HMMA GEMM core ===========================
constexpr int ROW_B  = 64;
constexpr int COMP_B = 128 * ROW_B;   // 8192 B per component tile
constexpr int STG_B  = 4 * COMP_B;    // 32768 B (Ah,Al,Bh,Bl)
constexpr int NSTG   = 3;
constexpr int SMEM_SZ = NSTG * STG_B; // 98304 B -> 2 CTAs/SM
constexpr int TPAD   = 133;           // fp32 transpose-buffer row stride (words)

__device__ __forceinline__ void load_half(uint32_t base,
    const bf16* __restrict__ ah, const bf16* __restrict__ al,
    const bf16* __restrict__ bh, const bf16* __restrict__ bl,
    int bm, int bn, int kt, int K, int tid, int g0)
{
    const int r  = tid >> 2;
    const int c  = tid & 3;
    const int kc = kt * 32 + c * 8;
    const int cp = c ^ ((r >> 1) & 3);
#pragma unroll
    for (int g = g0; g < g0 + 2; g++) {
        const int row = r + g * 32;
        const uint32_t so = (uint32_t)row * ROW_B + cp * 16;
        const long ga = (long)(bm + row) * K + kc;
        const long gb = (long)(bn + row) * K + kc;
        cp16(base + so,              ah + ga);
        cp16(base + COMP_B + so,     al + ga);
        cp16(base + 2 * COMP_B + so, bh + gb);
        cp16(base + 3 * COMP_B + so, bl + gb);
    }
}

// epi: 0 = fp32 C @ coff; 1 = split digits Ch/Cl @ coff;
//      2 = V^T transposed split (batch derived from bm)
__device__ __forceinline__ void gemm_core(
    uint32_t sb, float* __restrict__ tsbuf, int tid,
    const bf16* __restrict__ Ah, const bf16* __restrict__ Al,
    const bf16* __restrict__ Bh, const bf16* __restrict__ Bl,
    int bm, int bn, int N, int K,
    int epi, float* __restrict__ C,
    bf16* __restrict__ Ch, bf16* __restrict__ Cl, long coff)
{
    const int lane = tid & 31, warp = tid >> 5;
    const int wm = warp >> 1, wn = warp & 1;
    const int nk = K >> 5;

    const uint32_t aRow = (uint32_t)(wm * 64 + (lane & 15));
    const uint32_t aSw  = (aRow >> 1) & 3;
    const uint32_t aC0  = (uint32_t)((lane >> 4) & 1);
    const uint32_t bRow0 = (uint32_t)((lane & 7) | (((lane >> 4) & 1) << 3));
    const uint32_t bRow = (uint32_t)(wn * 64) + bRow0;
    const uint32_t bSw  = (bRow0 >> 1) & 3;
    const uint32_t bC0  = (uint32_t)((lane >> 3) & 1);

    float acc[4][8][4];
#pragma unroll
    for (int i = 0; i < 4; i++)
#pragma unroll
        for (int j = 0; j < 8; j++)
#pragma unroll
            for (int q = 0; q < 4; q++) acc[i][j][q] = 0.0f;

#pragma unroll
    for (int s = 0; s < NSTG - 1; s++) {
        load_half(sb + s * STG_B, Ah, Al, Bh, Bl, bm, bn, s, K, tid, 0);
        load_half(sb + s * STG_B, Ah, Al, Bh, Bl, bm, bn, s, K, tid, 2);
        CP_COMMIT();
    }

    for (int kt = 0; kt < nk; kt++) {
        CP_WAIT(NSTG - 2);
        __syncthreads();

        const uint32_t st = sb + (kt % NSTG) * STG_B;
        const int nx = kt + NSTG - 1;
        const uint32_t nslot = sb + (nx % NSTG) * STG_B;
        const bool doLoad = (nx < nk);

        // ---- k16 = 0 ----
        {
            const uint32_t aCk = (aC0) ^ aSw;
            const uint32_t bCk = (bC0) ^ bSw;
            const uint32_t aAddr = st + aRow * ROW_B + aCk * 16;
            const uint32_t bAddr = st + 2 * COMP_B + bRow * ROW_B + bCk * 16;
            uint32_t ah[4][4], al[4][4], bh[4][4], bl[4][4];
#pragma unroll
            for (int mi = 0; mi < 4; mi++) {
                ldm4(ah[mi], aAddr + mi * 16 * ROW_B);
                ldm4(al[mi], aAddr + COMP_B + mi * 16 * ROW_B);
            }
#pragma unroll
            for (int nb = 0; nb < 4; nb++) {
                ldm4(bh[nb], bAddr + nb * 16 * ROW_B);
                ldm4(bl[nb], bAddr + COMP_B + nb * 16 * ROW_B);
            }
#pragma unroll
            for (int mi = 0; mi < 4; mi++)
#pragma unroll
                for (int ni = 0; ni < 8; ni++) {
                    const uint32_t* bhp = &bh[ni >> 1][(ni & 1) * 2];
                    const uint32_t* blp = &bl[ni >> 1][(ni & 1) * 2];
                    mma16816(acc[mi][ni], ah[mi], bhp);
                    mma16816(acc[mi][ni], ah[mi], blp);
                    mma16816(acc[mi][ni], al[mi], bhp);
                }
        }

        if (doLoad)
            load_half(nslot, Ah, Al, Bh, Bl, bm, bn, nx, K, tid, 0);

        // ---- k16 = 1 ----
        {
            const uint32_t aCk = (2u + aC0) ^ aSw;
            const uint32_t bCk = (2u + bC0) ^ bSw;
            const uint32_t aAddr = st + aRow * ROW_B + aCk * 16;
            const uint32_t bAddr = st + 2 * COMP_B + bRow * ROW_B + bCk * 16;
            uint32_t ah[4][4], al[4][4], bh[4][4], bl[4][4];
#pragma unroll
            for (int mi = 0; mi < 4; mi++) {
                ldm4(ah[mi], aAddr + mi * 16 * ROW_B);
                ldm4(al[mi], aAddr + COMP_B + mi * 16 * ROW_B);
            }
#pragma unroll
            for (int nb = 0; nb < 4; nb++) {
                ldm4(bh[nb], bAddr + nb * 16 * ROW_B);
                ldm4(bl[nb], bAddr + COMP_B + nb * 16 * ROW_B);
            }

            if (doLoad)
                load_half(nslot, Ah, Al, Bh, Bl, bm, bn, nx, K, tid, 2);
            CP_COMMIT();   // unconditional: exact group accounting

#pragma unroll
            for (int mi = 0; mi < 4; mi++)
#pragma unroll
                for (int ni = 0; ni < 8; ni++) {
                    const uint32_t* bhp = &bh[ni >> 1][(ni & 1) * 2];
                    const uint32_t* blp = &bl[ni >> 1][(ni & 1) * 2];
                    mma16816(acc[mi][ni], ah[mi], bhp);
                    mma16816(acc[mi][ni], ah[mi], blp);
                    mma16816(acc[mi][ni], al[mi], bhp);
                }
        }
    }

    const int qr = lane >> 2, qc = (lane & 3) * 2;

    if (epi == 2) {
        // ---- transposed split epilogue (V^T digits) ----
        __syncthreads();
#pragma unroll
        for (int mi = 0; mi < 4; mi++)
#pragma unroll
            for (int ni = 0; ni < 8; ni++) {
                const int m = wm * 64 + mi * 16 + qr;
                const int n = wn * 64 + ni * 8 + qc;
                tsbuf[m * TPAD + n]           = acc[mi][ni][0];
                tsbuf[m * TPAD + n + 1]       = acc[mi][ni][1];
                tsbuf[(m + 8) * TPAD + n]     = acc[mi][ni][2];
                tsbuf[(m + 8) * TPAD + n + 1] = acc[mi][ni][3];
            }
        __syncthreads();
        const long DS = (long)D_DIM * S_LEN;
        const int zb = bm >> 11;
        const int mloc = bm & 2047;
        bf16* oh = Ch + (long)zb * DS;
        bf16* ol = Cl + (long)zb * DS;
        for (int k = 0; k < 32; k++) {
            const int n = warp + 4 * k;
            const long base = (long)(bn + n) * S_LEN + mloc;
#pragma unroll
            for (int j = 0; j < 4; j++) {
                const int m = lane + 32 * j;
                float f = tsbuf[m * TPAD + n];
                bf16 h = __float2bfloat16(f);
                oh[base + m] = h;
                ol[base + m] = __float2bfloat16(f - __bfloat162float(h));
            }
        }
        return;
    }

#pragma unroll
    for (int mi = 0; mi < 4; mi++)
#pragma unroll
        for (int ni = 0; ni < 8; ni++) {
            const int m = bm + wm * 64 + mi * 16 + qr;
            const int n = bn + wn * 64 + ni * 8 + qc;
            const long o0 = coff + (long)m * N + n;
            const long o1 = o0 + 8L * N;
            if (epi == 0) {
                *(float2*)(C + o0) = make_float2(acc[mi][ni][0], acc[mi][ni][1]);
                *(float2*)(C + o1) = make_float2(acc[mi][ni][2], acc[mi][ni][3]);
            } else {
                float x0 = acc[mi][ni][0], y0 = acc[mi][ni][1];
                float x1 = acc[mi][ni][2], y1 = acc[mi][ni][3];
                bf16 hx0 = __float2bfloat16(x0), hy0 = __float2bfloat16(y0);
                bf16 hx1 = __float2bfloat16(x1), hy1 = __float2bfloat16(y1);
                *(__nv_bfloat162*)(Ch + o0) = __nv_bfloat162(hx0, hy0);
                *(__nv_bfloat162*)(Ch + o1) = __nv_bfloat162(hx1, hy1);
                *(__nv_bfloat162*)(Cl + o0) = __nv_bfloat162(
                    __float2bfloat16(x0 - __bfloat162float(hx0)),
                    __float2bfloat16(y0 - __bfloat162float(hy0)));
                *(__nv_bfloat162*)(Cl + o1) = __nv_bfloat162(
                    __float2bfloat16(x1 - __bfloat162float(hx1)),
                    __float2bfloat16(y1 - __bfloat162float(hy1)));
            }
        }
}

// batched GEMM over blockIdx.{x,y,z} (used for AV)
__global__ void __launch_bounds__(128, 2)
gemm_b(const bf16* __restrict__ Agh, const bf16* __restrict__ Agl,
       const bf16* __restrict__ Bgh, const bf16* __restrict__ Bgl,
       float* __restrict__ C, int N, int K, long sA, long sB, long sC)
{
    extern __shared__ __align__(128) char smem[];
    const int z = blockIdx.z;
    gemm_core(smem_u32(smem), (float*)smem, threadIdx.x,
              Agh + (long)z * sA, Agl + (long)z * sA,
              Bgh + (long)z * sB, Bgl + (long)z * sB,
              blockIdx.y * 128, blockIdx.x * 128, N, K,
              0, C, nullptr, nullptr, (long)z * sC);
}

// ====== tail-filled phase kernels: main op + V-projection filler jobs =======
template <int MODE>
__global__ void __launch_bounds__(128, 2)
gemm_mix(const bf16* __restrict__ xh, const bf16* __restrict__ xl,
         const bf16* __restrict__ wqh, const bf16* __restrict__ wql,
         const bf16* __restrict__ wkh, const bf16* __restrict__ wkl,
         const bf16* __restrict__ wvth, const bf16* __restrict__ wvtl,
         const bf16* __restrict__ mh, const bf16* __restrict__ ml,
         const bf16* __restrict__ th, const bf16* __restrict__ tl,
         bf16* __restrict__ vth, bf16* __restrict__ vtl,
         bf16* __restrict__ outMh, bf16* __restrict__ outMl,
         bf16* __restrict__ outTh, bf16* __restrict__ outTl,
         float* __restrict__ sc,
         int nMain, int vBase)
{
    extern __shared__ __align__(128) char smem[];
    const uint32_t sb = smem_u32(smem);
    float* tsb = (float*)smem;
    const int b = blockIdx.x, tid = threadIdx.x;

    if (b >= nMain) {
        const int vj = vBase + (b - nMain);
        gemm_core(sb, tsb, tid, xh, xl, wvth, wvtl,
                  (vj >> 3) * 128, (vj & 7) * 128, D_DIM, D_DIM,
                  2, nullptr, vth, vtl, 0);
        return;
    }
    if (MODE == 1) {
        gemm_core(sb, tsb, tid, wkh, wkl, wqh, wql,
                  (b >> 3) * 128, (b & 7) * 128, D_DIM, D_DIM,
                  1, nullptr, outMh, outMl, 0);
    } else if (MODE == 2) {
        gemm_core(sb, tsb, tid, xh, xl, mh, ml,
                  (b >> 3) * 128, (b & 7) * 128, D_DIM, D_DIM,
                  1, nullptr, outTh, outTl, 0);
    } else {
        const long SD = (long)S_LEN * D_DIM, SS = (long)S_LEN * S_LEN;
        const int z = b >> 8, r = b & 255;
        gemm_core(sb, tsb, tid, th + (long)z * SD, tl + (long)z * SD,
                  xh + (long)z * SD, xl + (long)z * SD,
                  (r >> 4) * 128, (r & 15) * 128, S_LEN, D_DIM,
                  0, sc, nullptr, nullptr, (long)z * SS);
    }
}

// =========================== fused prep kernel ==============================
__global__ void __launch_bounds__(256)
prep_all(const float* __restrict__ x, const float* __restrict__ Wq,
         const float* __restrict__ Wk, const float* __restrict__ Wv,
         bf16* __restrict__ xh, bf16* __restrict__ xl,
         bf16* __restrict__ wqh, bf16* __restrict__ wql,
         bf16* __restrict__ wkh, bf16* __restrict__ wkl,
         bf16* __restrict__ wvth, bf16* __restrict__ wvtl)
{
    __shared__ float t[32][33];
    const int b = blockIdx.x;
    if (b < 8192) {
        long i = ((long)b * 256 + threadIdx.x) * 4;
        float4 f = *(const float4*)(x + i);
        bf16 h0 = __float2bfloat16(f.x), h1 = __float2bfloat16(f.y);
        bf16 h2 = __float2bfloat16(f.z), h3 = __float2bfloat16(f.w);
        __nv_bfloat162* hp = (__nv_bfloat162*)(xh + i);
        __nv_bfloat162* lp = (__nv_bfloat162*)(xl + i);
        hp[0] = __nv_bfloat162(h0, h1);
        hp[1] = __nv_bfloat162(h2, h3);
        lp[0] = __nv_bfloat162(__float2bfloat16(f.x - __bfloat162float(h0)),
                               __float2bfloat16(f.y - __bfloat162float(h1)));
        lp[1] = __nv_bfloat162(__float2bfloat16(f.z - __bfloat162float(h2)),
                               __float2bfloat16(f.w - __bfloat162float(h3)));
        return;
    }
    const int j = b - 8192;
    const int z = j >> 10;
    const int r = j & 1023;
    const int bx = (r & 31) * 32, by = (r >> 5) * 32;
    const int tx = threadIdx.x & 31, ty = threadIdx.x >> 5;
    if (z < 2) {
        const float* ip = (z == 0) ? Wq : Wk;
        bf16* oh = (z == 0) ? wqh : wkh;
        bf16* ol = (z == 0) ? wql : wkl;
#pragma unroll
        for (int i = ty; i < 32; i += 8) {
            long o = (long)(by + i) * D_DIM + bx + tx;
            float f = ip[o];
            bf16 h = __float2bfloat16(f);
            oh[o] = h;
            ol[o] = __float2bfloat16(f - __bfloat162float(h));
        }
    } else {
#pragma unroll
        for (int i = ty; i < 32; i += 8)
            t[i][tx] = Wv[(long)(by + i) * D_DIM + bx + tx];
        __syncthreads();
#pragma unroll
        for (int i = ty; i < 32; i += 8) {
            float f = t[tx][i];
            bf16 h = __float2bfloat16(f);
            long o = (long)(bx + i) * D_DIM + by + tx;
            wvth[o] = h;
            wvtl[o] = __float2bfloat16(f - __bfloat162float(h));
        }
    }
}

// ============================ softmax =======================================
__device__ __forceinline__ float warpMax(float v) {
#pragma unroll
    for (int o = 16; o; o >>= 1) v = fmaxf(v, __shfl_xor_sync(0xFFFFFFFFu, v, o));
    return v;
}
__device__ __forceinline__ float warpSum(float v) {
#pragma unroll
    for (int o = 16; o; o >>= 1) v += __shfl_xor_sync(0xFFFFFFFFu, v, o);
    return v;
}

struct alignas(8) bf16x4 { __nv_bfloat162 a, b; };

__global__ void softmax_rows(const float* __restrict__ Sc,
                             bf16* __restrict__ Wh, bf16* __restrict__ Wl)
{
    __shared__ float red[8];
    const long row = blockIdx.x;
    const float4* p4 = (const float4*)(Sc + row * (long)S_LEN);
    const int tid = threadIdx.x;
    const float scale = 0.03125f;  // 1/sqrt(1024)

    float4 va = p4[tid], vb = p4[tid + 256];
    float v[8] = {va.x, va.y, va.z, va.w, vb.x, vb.y, vb.z, vb.w};
    float mx = -3.402823e38f;
#pragma unroll
    for (int i = 0; i < 8; i++) { v[i] *= scale; mx = fmaxf(mx, v[i]); }
    mx = warpMax(mx);
    if ((tid & 31) == 0) red[tid >> 5] = mx;
    __syncthreads();
    if (tid < 32) {
        float m = (tid < 8) ? red[tid] : -3.402823e38f;
        m = warpMax(m);
        if (tid == 0) red[0] = m;
    }
    __syncthreads();
    mx = red[0];
    __syncthreads();

    float s = 0.0f;
#pragma unroll
    for (int i = 0; i < 8; i++) { v[i] = fexp(v[i] - mx); s += v[i]; }
    s = warpSum(s);
    if ((tid & 31) == 0) red[tid >> 5] = s;
    __syncthreads();
    if (tid < 32) {
        float t = (tid < 8) ? red[tid] : 0.0f;
        t = warpSum(t);
        if (tid == 0) red[0] = t;
    }
    __syncthreads();
    const float inv = 1.0f / red[0];

    bf16 h[8], l[8];
#pragma unroll
    for (int i = 0; i < 8; i++) {
        float w = v[i] * inv;
        h[i] = __float2bfloat16(w);
        l[i] = __float2bfloat16(w - __bfloat162float(h[i]));
    }
    bf16x4* wh4 = (bf16x4*)(Wh + row * (long)S_LEN);
    bf16x4* wl4 = (bf16x4*)(Wl + row * (long)S_LEN);
    wh4[tid]       = {__nv_bfloat162(h[0], h[1]), __nv_bfloat162(h[2], h[3])};
    wh4[tid + 256] = {__nv_bfloat162(h[4], h[5]), __nv_bfloat162(h[6], h[7])};
    wl4[tid]       = {__nv_bfloat162(l[0], l[1]), __nv_bfloat162(l[2], l[3])};
    wl4[tid + 256] = {__nv_bfloat162(l[4], l[5]), __nv_bfloat162(l[6], l[7])};
}

// ============================ host side =====================================
extern "C" void kernel_launch(void* const* d_in, const int* in_sizes, int n_in,
                              void* d_out, int out_size)
{
    const float* x  = (const float*)d_in[0];
    const float* Wq = (const float*)d_in[1];
    const float* Wk = (const float*)d_in[2];
    const float* Wv = (const float*)d_in[3];
    float* out = (float*)d_out;

    void *xh, *xl, *wqh, *wql, *wkh, *wkl, *wvth, *wvtl, *mh, *ml, *th, *tl;
    void *vth, *vtl, *sc, *wh, *wl;
    cudaGetSymbolAddress(&xh, g_xh);     cudaGetSymbolAddress(&xl, g_xl);
    cudaGetSymbolAddress(&wqh, g_wqh);   cudaGetSymbolAddress(&wql, g_wql);
    cudaGetSymbolAddress(&wkh, g_wkh);   cudaGetSymbolAddress(&wkl, g_wkl);
    cudaGetSymbolAddress(&wvth, g_wvth); cudaGetSymbolAddress(&wvtl, g_wvtl);
    cudaGetSymbolAddress(&mh, g_mh);     cudaGetSymbolAddress(&ml, g_ml);
    cudaGetSymbolAddress(&th, g_th);     cudaGetSymbolAddress(&tl, g_tl);
    cudaGetSymbolAddress(&vth, g_vth);   cudaGetSymbolAddress(&vtl, g_vtl);
    cudaGetSymbolAddress(&sc, g_sc);
    cudaGetSymbolAddress(&wh, g_wh);     cudaGetSymbolAddress(&wl, g_wl);

    cudaFuncSetAttribute(gemm_b,      cudaFuncAttributeMaxDynamicSharedMemorySize, SMEM_SZ);
    cudaFuncSetAttribute(gemm_mix<1>, cudaFuncAttributeMaxDynamicSharedMemorySize, SMEM_SZ);
    cudaFuncSetAttribute(gemm_mix<2>, cudaFuncAttributeMaxDynamicSharedMemorySize, SMEM_SZ);
    cudaFuncSetAttribute(gemm_mix<3>, cudaFuncAttributeMaxDynamicSharedMemorySize, SMEM_SZ);

    // V-job distribution: fill each phase launch to its ceil boundary
    int nsm = 148;
    cudaDeviceGetAttribute(&nsm, cudaDevAttrMultiProcessorCount, 0);
    const int slots = 2 * nsm;
    auto cap = [slots](int jobs) { return ((jobs + slots - 1) / slots) * slots - jobs; };
    int rem = 512;
    int v1 = rem < (slots - 64) ? rem : (slots - 64); rem -= v1;
    int v2 = rem < cap(512)  ? rem : cap(512);        rem -= v2;
    int v3 = rem < cap(1024) ? rem : cap(1024);       rem -= v3;
    v3 += rem;   // leftover (accepts +1 wave on the largest launch)

    const long SD = (long)S_LEN * D_DIM, SS = (long)S_LEN * S_LEN;

    // ---- fused data prep (x split + all weight digits) ----
    prep_all<<<8192 + 3 * 1024, 256>>>(x, Wq, Wk, Wv,
        (bf16*)xh, (bf16*)xl, (bf16*)wqh, (bf16*)wql,
        (bf16*)wkh, (bf16*)wkl, (bf16*)wvth, (bf16*)wvtl);

    // ---- L1: M' (64) + V filler ----
    gemm_mix<1><<<64 + v1, 128, SMEM_SZ>>>(
        (bf16*)xh, (bf16*)xl, (bf16*)wqh, (bf16*)wql, (bf16*)wkh, (bf16*)wkl,
        (bf16*)wvth, (bf16*)wvtl, (bf16*)mh, (bf16*)ml, (bf16*)th, (bf16*)tl,
        (bf16*)vth, (bf16*)vtl, (bf16*)mh, (bf16*)ml, (bf16*)th, (bf16*)tl,
        (float*)sc, 64, 0);

    // ---- L2: T (512) + V filler ----
    gemm_mix<2><<<512 + v2, 128, SMEM_SZ>>>(
        (bf16*)xh, (bf16*)xl, (bf16*)wqh, (bf16*)wql, (bf16*)wkh, (bf16*)wkl,
        (bf16*)wvth, (bf16*)wvtl, (bf16*)mh, (bf16*)ml, (bf16*)th, (bf16*)tl,
        (bf16*)vth, (bf16*)vtl, (bf16*)mh, (bf16*)ml, (bf16*)th, (bf16*)tl,
        (float*)sc, 512, v1);

    // ---- L3: scores (1024) + V filler ----
    gemm_mix<3><<<1024 + v3, 128, SMEM_SZ>>>(
        (bf16*)xh, (bf16*)xl, (bf16*)wqh, (bf16*)wql, (bf16*)wkh, (bf16*)wkl,
        (bf16*)wvth, (bf16*)wvtl, (bf16*)mh, (bf16*)ml, (bf16*)th, (bf16*)tl,
        (bf16*)vth, (bf16*)vtl, (bf16*)mh, (bf16*)ml, (bf16*)th, (bf16*)tl,
        (float*)sc, 1024, v1 + v2);

    softmax_rows<<<BATCH * S_LEN, 256>>>((const float*)sc, (bf16*)wh, (bf16*)wl);

    // ---- AV: out = softmaxW * V ----
    gemm_b<<<dim3(D_DIM / 128, S_LEN / 128, BATCH), 128, SMEM_SZ>>>(
        (bf16*)wh, (bf16*)wl, (bf16*)vth, (bf16*)vtl,
        out, D_DIM, S_LEN, SS, SD, SD);
}

// round 16
// speedup vs baseline: 1.0055x; 1.0055x over previous
#include <cuda_runtime.h>
#include <cuda_bf16.h>
#include <cstdint>

#define S_LEN 2048
#define D_DIM 1024
#define BATCH 4
#define MTOT  (BATCH * S_LEN)   // 8192

typedef __nv_bfloat16 bf16;

// ============================ device scratch ================================
__device__ bf16  g_xh [(size_t)MTOT * D_DIM];
__device__ bf16  g_xl [(size_t)MTOT * D_DIM];
__device__ bf16  g_wqh[(size_t)D_DIM * D_DIM];   // Wq digits (native layout)
__device__ bf16  g_wql[(size_t)D_DIM * D_DIM];
__device__ bf16  g_wkh[(size_t)D_DIM * D_DIM];   // Wk digits (native layout)
__device__ bf16  g_wkl[(size_t)D_DIM * D_DIM];
__device__ bf16  g_wvth[(size_t)D_DIM * D_DIM];  // Wv^T digits
__device__ bf16  g_wvtl[(size_t)D_DIM * D_DIM];
__device__ bf16  g_mh [(size_t)D_DIM * D_DIM];   // M' = Wk Wq^T digits
__device__ bf16  g_ml [(size_t)D_DIM * D_DIM];
__device__ bf16  g_th [(size_t)MTOT * D_DIM];    // T = x M'^T digits
__device__ bf16  g_tl [(size_t)MTOT * D_DIM];
__device__ bf16  g_vth[(size_t)BATCH * D_DIM * S_LEN];  // V^T digits per batch
__device__ bf16  g_vtl[(size_t)BATCH * D_DIM * S_LEN];
__device__ float g_sc [(size_t)BATCH * S_LEN * S_LEN];
__device__ bf16  g_wh [(size_t)BATCH * S_LEN * S_LEN];
__device__ bf16  g_wl [(size_t)BATCH * S_LEN * S_LEN];

// ============================ PTX helpers ===================================
__device__ __forceinline__ uint32_t smem_u32(const void* p) {
    uint32_t a;
    asm("{ .reg .u64 t; cvta.to.shared.u64 t, %1; cvt.u32.u64 %0, t; }" : "=r"(a) : "l"(p));
    return a;
}
__device__ __forceinline__ void cp16(uint32_t s, const void* g) {
    asm volatile("cp.async.cg.shared.global [%0], [%1], 16;" :: "r"(s), "l"(g) : "memory");
}
#define CP_COMMIT() asm volatile("cp.async.commit_group;" ::: "memory")
#define CP_WAIT(n)  asm volatile("cp.async.wait_group %0;" :: "n"(n) : "memory")

__device__ __forceinline__ void ldm4(uint32_t r[4], uint32_t a) {
    asm volatile("ldmatrix.sync.aligned.m8n8.x4.shared.b16 {%0,%1,%2,%3}, [%4];"
                 : "=r"(r[0]), "=r"(r[1]), "=r"(r[2]), "=r"(r[3]) : "r"(a));
}
__device__ __forceinline__ void mma16816(float c[4], const uint32_t a[4], const uint32_t b[2]) {
    asm volatile("mma.sync.aligned.m16n8k16.row.col.f32.bf16.bf16.f32 "
                 "{%0,%1,%2,%3}, {%4,%5,%6,%7}, {%8,%9}, {%0,%1,%2,%3};"
                 : "+f"(c[0]), "+f"(c[1]), "+f"(c[2]), "+f"(c[3])
                 : "r"(a[0]), "r"(a[1]), "r"(a[2]), "r"(a[3]), "r"(b[0]), "r"(b[1]));
}

// fast exp on fma/alu pipes (no MUFU). Valid for x in [-80, 0.5]; rel err ~5e-8.
__device__ __forceinline__ float fexp(float x) {
    x = fmaxf(x, -80.0f);
    const float MAGIC = 12582912.0f;            // 1.5 * 2^23
    float t = fmaf(x, 1.4426950408889634f, MAGIC);
    int   ni = __float_as_int(t) - 0x4B400000;
    float n = t - MAGIC;
    float r = fmaf(n, -0.6931471824645996f, x);
    r = fmaf(n, 1.9046542121259336e-9f, r);
    float p = 1.3888889e-3f;
    p = fmaf(p, r, 8.3333333e-3f);
    p = fmaf(p, r, 4.1666667e-2f);
    p = fmaf(p, r, 1.6666667e-1f);
    p = fmaf(p, r, 0.5f);
    p = fmaf(p, r, 1.0f);
    p = fmaf(p, r, 1.0f);
    return __int_as_float(__float_as_int(p) + (ni << 23));
}

// ====================== split-bf16 HMMA GEMM core ===========================
constexpr int ROW_B  = 64;
constexpr int COMP_B = 128 * ROW_B;   // 8192 B per component tile
constexpr int STG_B  = 4 * COMP_B;    // 32768 B (Ah,Al,Bh,Bl)
constexpr int NSTG   = 3;
constexpr int SMEM_SZ = NSTG * STG_B; // 98304 B -> 2 CTAs/SM
constexpr int TPAD   = 133;           // fp32 transpose-buffer row stride (words)

__device__ __forceinline__ void load_half(uint32_t base,
    const bf16* __restrict__ ah, const bf16* __restrict__ al,
    const bf16* __restrict__ bh, const bf16* __restrict__ bl,
    int bm, int bn, int kt, int K, int tid, int g0)
{
    const int r  = tid >> 2;
    const int c  = tid & 3;
    const int kc = kt * 32 + c * 8;
    const int cp = c ^ ((r >> 1) & 3);
#pragma unroll
    for (int g = g0; g < g0 + 2; g++) {
        const int row = r + g * 32;
        const uint32_t so = (uint32_t)row * ROW_B + cp * 16;
        const long ga = (long)(bm + row) * K + kc;
        const long gb = (long)(bn + row) * K + kc;
        cp16(base + so,              ah + ga);
        cp16(base + COMP_B + so,     al + ga);
        cp16(base + 2 * COMP_B + so, bh + gb);
        cp16(base + 3 * COMP_B + so, bl + gb);
    }
}

// epi: 0 = fp32 C @ coff; 1 = split digits Ch/Cl @ coff;
//      2 = V^T transposed split (batch derived from bm)
__device__ __forceinline__ void gemm_core(
    uint32_t sb, float* __restrict__ tsbuf, int tid,
    const bf16* __restrict__ Ah, const bf16* __restrict__ Al,
    const bf16* __restrict__ Bh, const bf16* __restrict__ Bl,
    int bm, int bn, int N, int K,
    int epi, float* __restrict__ C,
    bf16* __restrict__ Ch, bf16* __restrict__ Cl, long coff)
{
    const int lane = tid & 31, warp = tid >> 5;
    const int wm = warp >> 1, wn = warp & 1;
    const int nk = K >> 5;

    const uint32_t aRow = (uint32_t)(wm * 64 + (lane & 15));
    const uint32_t aSw  = (aRow >> 1) & 3;
    const uint32_t aC0  = (uint32_t)((lane >> 4) & 1);
    const uint32_t bRow0 = (uint32_t)((lane & 7) | (((lane >> 4) & 1) << 3));
    const uint32_t bRow = (uint32_t)(wn * 64) + bRow0;
    const uint32_t bSw  = (bRow0 >> 1) & 3;
    const uint32_t bC0  = (uint32_t)((lane >> 3) & 1);

    float acc[4][8][4];
#pragma unroll
    for (int i = 0; i < 4; i++)
#pragma unroll
        for (int j = 0; j < 8; j++)
#pragma unroll
            for (int q = 0; q < 4; q++) acc[i][j][q] = 0.0f;

#pragma unroll
    for (int s = 0; s < NSTG - 1; s++) {
        load_half(sb + s * STG_B, Ah, Al, Bh, Bl, bm, bn, s, K, tid, 0);
        load_half(sb + s * STG_B, Ah, Al, Bh, Bl, bm, bn, s, K, tid, 2);
        CP_COMMIT();
    }

    for (int kt = 0; kt < nk; kt++) {
        CP_WAIT(NSTG - 2);
        __syncthreads();

        const uint32_t st = sb + (kt % NSTG) * STG_B;
        const int nx = kt + NSTG - 1;
        const uint32_t nslot = sb + (nx % NSTG) * STG_B;
        const bool doLoad = (nx < nk);

        // ---- k16 = 0 ----
        {
            const uint32_t aCk = (aC0) ^ aSw;
            const uint32_t bCk = (bC0) ^ bSw;
            const uint32_t aAddr = st + aRow * ROW_B + aCk * 16;
            const uint32_t bAddr = st + 2 * COMP_B + bRow * ROW_B + bCk * 16;
            uint32_t ah[4][4], al[4][4], bh[4][4], bl[4][4];
#pragma unroll
            for (int mi = 0; mi < 4; mi++) {
                ldm4(ah[mi], aAddr + mi * 16 * ROW_B);
                ldm4(al[mi], aAddr + COMP_B + mi * 16 * ROW_B);
            }
#pragma unroll
            for (int nb = 0; nb < 4; nb++) {
                ldm4(bh[nb], bAddr + nb * 16 * ROW_B);
                ldm4(bl[nb], bAddr + COMP_B + nb * 16 * ROW_B);
            }
#pragma unroll
            for (int mi = 0; mi < 4; mi++)
#pragma unroll
                for (int ni = 0; ni < 8; ni++) {
                    const uint32_t* bhp = &bh[ni >> 1][(ni & 1) * 2];
                    const uint32_t* blp = &bl[ni >> 1][(ni & 1) * 2];
                    mma16816(acc[mi][ni], ah[mi], bhp);
                    mma16816(acc[mi][ni], ah[mi], blp);
                    mma16816(acc[mi][ni], al[mi], bhp);
                }
        }

        if (doLoad)
            load_half(nslot, Ah, Al, Bh, Bl, bm, bn, nx, K, tid, 0);

        // ---- k16 = 1 ----
        {
            const uint32_t aCk = (2u + aC0) ^ aSw;
            const uint32_t bCk = (2u + bC0) ^ bSw;
            const uint32_t aAddr = st + aRow * ROW_B + aCk * 16;
            const uint32_t bAddr = st + 2 * COMP_B + bRow * ROW_B + bCk * 16;
            uint32_t ah[4][4], al[4][4], bh[4][4], bl[4][4];
#pragma unroll
            for (int mi = 0; mi < 4; mi++) {
                ldm4(ah[mi], aAddr + mi * 16 * ROW_B);
                ldm4(al[mi], aAddr + COMP_B + mi * 16 * ROW_B);
            }
#pragma unroll
            for (int nb = 0; nb < 4; nb++) {
                ldm4(bh[nb], bAddr + nb * 16 * ROW_B);
                ldm4(bl[nb], bAddr + COMP_B + nb * 16 * ROW_B);
            }

            if (doLoad)
                load_half(nslot, Ah, Al, Bh, Bl, bm, bn, nx, K, tid, 2);
            CP_COMMIT();   // unconditional: exact group accounting

#pragma unroll
            for (int mi = 0; mi < 4; mi++)
#pragma unroll
                for (int ni = 0; ni < 8; ni++) {
                    const uint32_t* bhp = &bh[ni >> 1][(ni & 1) * 2];
                    const uint32_t* blp = &bl[ni >> 1][(ni & 1) * 2];
                    mma16816(acc[mi][ni], ah[mi], bhp);
                    mma16816(acc[mi][ni], ah[mi], blp);
                    mma16816(acc[mi][ni], al[mi], bhp);
                }
        }
    }

    const int qr = lane >> 2, qc = (lane & 3) * 2;

    if (epi == 2) {
        // ---- transposed split epilogue (V^T digits) ----
        __syncthreads();
#pragma unroll
        for (int mi = 0; mi < 4; mi++)
#pragma unroll
            for (int ni = 0; ni < 8; ni++) {
                const int m = wm * 64 + mi * 16 + qr;
                const int n = wn * 64 + ni * 8 + qc;
                tsbuf[m * TPAD + n]           = acc[mi][ni][0];
                tsbuf[m * TPAD + n + 1]       = acc[mi][ni][1];
                tsbuf[(m + 8) * TPAD + n]     = acc[mi][ni][2];
                tsbuf[(m + 8) * TPAD + n + 1] = acc[mi][ni][3];
            }
        __syncthreads();
        const long DS = (long)D_DIM * S_LEN;
        const int zb = bm >> 11;
        const int mloc = bm & 2047;
        bf16* oh = Ch + (long)zb * DS;
        bf16* ol = Cl + (long)zb * DS;
        for (int k = 0; k < 32; k++) {
            const int n = warp + 4 * k;
            const long base = (long)(bn + n) * S_LEN + mloc;
#pragma unroll
            for (int j = 0; j < 4; j++) {
                const int m = lane + 32 * j;
                float f = tsbuf[m * TPAD + n];
                bf16 h = __float2bfloat16(f);
                oh[base + m] = h;
                ol[base + m] = __float2bfloat16(f - __bfloat162float(h));
            }
        }
        return;
    }

#pragma unroll
    for (int mi = 0; mi < 4; mi++)
#pragma unroll
        for (int ni = 0; ni < 8; ni++) {
            const int m = bm + wm * 64 + mi * 16 + qr;
            const int n = bn + wn * 64 + ni * 8 + qc;
            const long o0 = coff + (long)m * N + n;
            const long o1 = o0 + 8L * N;
            if (epi == 0) {
                *(float2*)(C + o0) = make_float2(acc[mi][ni][0], acc[mi][ni][1]);
                *(float2*)(C + o1) = make_float2(acc[mi][ni][2], acc[mi][ni][3]);
            } else {
                float x0 = acc[mi][ni][0], y0 = acc[mi][ni][1];
                float x1 = acc[mi][ni][2], y1 = acc[mi][ni][3];
                bf16 hx0 = __float2bfloat16(x0), hy0 = __float2bfloat16(y0);
                bf16 hx1 = __float2bfloat16(x1), hy1 = __float2bfloat16(y1);
                *(__nv_bfloat162*)(Ch + o0) = __nv_bfloat162(hx0, hy0);
                *(__nv_bfloat162*)(Ch + o1) = __nv_bfloat162(hx1, hy1);
                *(__nv_bfloat162*)(Cl + o0) = __nv_bfloat162(
                    __float2bfloat16(x0 - __bfloat162float(hx0)),
                    __float2bfloat16(y0 - __bfloat162float(hy0)));
                *(__nv_bfloat162*)(Cl + o1) = __nv_bfloat162(
                    __float2bfloat16(x1 - __bfloat162float(hx1)),
                    __float2bfloat16(y1 - __bfloat162float(hy1)));
            }
        }
}

// batched GEMM over blockIdx.{x,y,z} (used for AV)
__global__ void __launch_bounds__(128, 2)
gemm_b(const bf16* __restrict__ Agh, const bf16* __restrict__ Agl,
       const bf16* __restrict__ Bgh, const bf16* __restrict__ Bgl,
       float* __restrict__ C, int N, int K, long sA, long sB, long sC)
{
    extern __shared__ __align__(128) char smem[];
    const int z = blockIdx.z;
    gemm_core(smem_u32(smem), (float*)smem, threadIdx.x,
              Agh + (long)z * sA, Agl + (long)z * sA,
              Bgh + (long)z * sB, Bgl + (long)z * sB,
              blockIdx.y * 128, blockIdx.x * 128, N, K,
              0, C, nullptr, nullptr, (long)z * sC);
}

// ====== tail-filled phase kernels: main op + V-projection filler jobs =======
template <int MODE>
__global__ void __launch_bounds__(128, 2)
gemm_mix(const bf16* __restrict__ xh, const bf16* __restrict__ xl,
         const bf16* __restrict__ wqh, const bf16* __restrict__ wql,
         const bf16* __restrict__ wkh, const bf16* __restrict__ wkl,
         const bf16* __restrict__ wvth, const bf16* __restrict__ wvtl,
         const bf16* __restrict__ mh, const bf16* __restrict__ ml,
         const bf16* __restrict__ th, const bf16* __restrict__ tl,
         bf16* __restrict__ vth, bf16* __restrict__ vtl,
         bf16* __restrict__ outMh, bf16* __restrict__ outMl,
         bf16* __restrict__ outTh, bf16* __restrict__ outTl,
         float* __restrict__ sc,
         int nMain, int vBase)
{
    extern __shared__ __align__(128) char smem[];
    const uint32_t sb = smem_u32(smem);
    float* tsb = (float*)smem;
    const int b = blockIdx.x, tid = threadIdx.x;

    if (b >= nMain) {
        const int vj = vBase + (b - nMain);
        gemm_core(sb, tsb, tid, xh, xl, wvth, wvtl,
                  (vj >> 3) * 128, (vj & 7) * 128, D_DIM, D_DIM,
                  2, nullptr, vth, vtl, 0);
        return;
    }
    if (MODE == 1) {
        gemm_core(sb, tsb, tid, wkh, wkl, wqh, wql,
                  (b >> 3) * 128, (b & 7) * 128, D_DIM, D_DIM,
                  1, nullptr, outMh, outMl, 0);
    } else if (MODE == 2) {
        gemm_core(sb, tsb, tid, xh, xl, mh, ml,
                  (b >> 3) * 128, (b & 7) * 128, D_DIM, D_DIM,
                  1, nullptr, outTh, outTl, 0);
    } else {
        const long SD = (long)S_LEN * D_DIM, SS = (long)S_LEN * S_LEN;
        const int z = b >> 8, r = b & 255;
        gemm_core(sb, tsb, tid, th + (long)z * SD, tl + (long)z * SD,
                  xh + (long)z * SD, xl + (long)z * SD,
                  (r >> 4) * 128, (r & 15) * 128, S_LEN, D_DIM,
                  0, sc, nullptr, nullptr, (long)z * SS);
    }
}

// =========================== fused prep kernel ==============================
__global__ void __launch_bounds__(256)
prep_all(const float* __restrict__ x, const float* __restrict__ Wq,
         const float* __restrict__ Wk, const float* __restrict__ Wv,
         bf16* __restrict__ xh, bf16* __restrict__ xl,
         bf16* __restrict__ wqh, bf16* __restrict__ wql,
         bf16* __restrict__ wkh, bf16* __restrict__ wkl,
         bf16* __restrict__ wvth, bf16* __restrict__ wvtl)
{
    __shared__ float t[32][33];
    const int b = blockIdx.x;
    if (b < 8192) {
        long i = ((long)b * 256 + threadIdx.x) * 4;
        float4 f = *(const float4*)(x + i);
        bf16 h0 = __float2bfloat16(f.x), h1 = __float2bfloat16(f.y);
        bf16 h2 = __float2bfloat16(f.z), h3 = __float2bfloat16(f.w);
        __nv_bfloat162* hp = (__nv_bfloat162*)(xh + i);
        __nv_bfloat162* lp = (__nv_bfloat162*)(xl + i);
        hp[0] = __nv_bfloat162(h0, h1);
        hp[1] = __nv_bfloat162(h2, h3);
        lp[0] = __nv_bfloat162(__float2bfloat16(f.x - __bfloat162float(h0)),
                               __float2bfloat16(f.y - __bfloat162float(h1)));
        lp[1] = __nv_bfloat162(__float2bfloat16(f.z - __bfloat162float(h2)),
                               __float2bfloat16(f.w - __bfloat162float(h3)));
        return;
    }
    const int j = b - 8192;
    const int z = j >> 10;
    const int r = j & 1023;
    const int bx = (r & 31) * 32, by = (r >> 5) * 32;
    const int tx = threadIdx.x & 31, ty = threadIdx.x >> 5;
    if (z < 2) {
        const float* ip = (z == 0) ? Wq : Wk;
        bf16* oh = (z == 0) ? wqh : wkh;
        bf16* ol = (z == 0) ? wql : wkl;
#pragma unroll
        for (int i = ty; i < 32; i += 8) {
            long o = (long)(by + i) * D_DIM + bx + tx;
            float f = ip[o];
            bf16 h = __float2bfloat16(f);
            oh[o] = h;
            ol[o] = __float2bfloat16(f - __bfloat162float(h));
        }
    } else {
#pragma unroll
        for (int i = ty; i < 32; i += 8)
            t[i][tx] = Wv[(long)(by + i) * D_DIM + bx + tx];
        __syncthreads();
#pragma unroll
        for (int i = ty; i < 32; i += 8) {
            float f = t[tx][i];
            bf16 h = __float2bfloat16(f);
            long o = (long)(bx + i) * D_DIM + by + tx;
            wvth[o] = h;
            wvtl[o] = __float2bfloat16(f - __bfloat162float(h));
        }
    }
}

// ============================ softmax =======================================
__device__ __forceinline__ float warpMax(float v) {
#pragma unroll
    for (int o = 16; o; o >>= 1) v = fmaxf(v, __shfl_xor_sync(0xFFFFFFFFu, v, o));
    return v;
}
__device__ __forceinline__ float warpSum(float v) {
#pragma unroll
    for (int o = 16; o; o >>= 1) v += __shfl_xor_sync(0xFFFFFFFFu, v, o);
    return v;
}

struct alignas(8) bf16x4 { __nv_bfloat162 a, b; };

// Warp-per-row softmax: 8 warps/block, each warp owns one full row in regs.
// No __syncthreads, no smem; all reductions via shfl.
__global__ void __launch_bounds__(256)
softmax_rows(const float* __restrict__ Sc,
             bf16* __restrict__ Wh, bf16* __restrict__ Wl)
{
    const int warp = threadIdx.x >> 5, lane = threadIdx.x & 31;
    const long row = (long)blockIdx.x * 8 + warp;
    const float4* p4 = (const float4*)(Sc + row * (long)S_LEN);
    const float scale = 0.03125f;  // 1/sqrt(1024)

    float v[64];
    float mx = -3.402823e38f;
#pragma unroll
    for (int j = 0; j < 16; j++) {
        float4 f = p4[lane + 32 * j];
        v[4 * j + 0] = f.x * scale; v[4 * j + 1] = f.y * scale;
        v[4 * j + 2] = f.z * scale; v[4 * j + 3] = f.w * scale;
        mx = fmaxf(mx, fmaxf(fmaxf(v[4 * j], v[4 * j + 1]),
                             fmaxf(v[4 * j + 2], v[4 * j + 3])));
    }
    mx = warpMax(mx);

    float s = 0.0f;
#pragma unroll
    for (int i = 0; i < 64; i++) { v[i] = fexp(v[i] - mx); s += v[i]; }
    s = warpSum(s);
    const float inv = 1.0f / s;

    bf16x4* wh4 = (bf16x4*)(Wh + row * (long)S_LEN);
    bf16x4* wl4 = (bf16x4*)(Wl + row * (long)S_LEN);
#pragma unroll
    for (int j = 0; j < 16; j++) {
        bf16 h[4], l[4];
#pragma unroll
        for (int q = 0; q < 4; q++) {
            float w = v[4 * j + q] * inv;
            h[q] = __float2bfloat16(w);
            l[q] = __float2bfloat16(w - __bfloat162float(h[q]));
        }
        wh4[lane + 32 * j] = {__nv_bfloat162(h[0], h[1]), __nv_bfloat162(h[2], h[3])};
        wl4[lane + 32 * j] = {__nv_bfloat162(l[0], l[1]), __nv_bfloat162(l[2], l[3])};
    }
}

// ============================ host side =====================================
extern "C" void kernel_launch(void* const* d_in, const int* in_sizes, int n_in,
                              void* d_out, int out_size)
{
    const float* x  = (const float*)d_in[0];
    const float* Wq = (const float*)d_in[1];
    const float* Wk = (const float*)d_in[2];
    const float* Wv = (const float*)d_in[3];
    float* out = (float*)d_out;

    void *xh, *xl, *wqh, *wql, *wkh, *wkl, *wvth, *wvtl, *mh, *ml, *th, *tl;
    void *vth, *vtl, *sc, *wh, *wl;
    cudaGetSymbolAddress(&xh, g_xh);     cudaGetSymbolAddress(&xl, g_xl);
    cudaGetSymbolAddress(&wqh, g_wqh);   cudaGetSymbolAddress(&wql, g_wql);
    cudaGetSymbolAddress(&wkh, g_wkh);   cudaGetSymbolAddress(&wkl, g_wkl);
    cudaGetSymbolAddress(&wvth, g_wvth); cudaGetSymbolAddress(&wvtl, g_wvtl);
    cudaGetSymbolAddress(&mh, g_mh);     cudaGetSymbolAddress(&ml, g_ml);
    cudaGetSymbolAddress(&th, g_th);     cudaGetSymbolAddress(&tl, g_tl);
    cudaGetSymbolAddress(&vth, g_vth);   cudaGetSymbolAddress(&vtl, g_vtl);
    cudaGetSymbolAddress(&sc, g_sc);
    cudaGetSymbolAddress(&wh, g_wh);     cudaGetSymbolAddress(&wl, g_wl);

    cudaFuncSetAttribute(gemm_b,      cudaFuncAttributeMaxDynamicSharedMemorySize, SMEM_SZ);
    cudaFuncSetAttribute(gemm_mix<1>, cudaFuncAttributeMaxDynamicSharedMemorySize, SMEM_SZ);
    cudaFuncSetAttribute(gemm_mix<2>, cudaFuncAttributeMaxDynamicSharedMemorySize, SMEM_SZ);
    cudaFuncSetAttribute(gemm_mix<3>, cudaFuncAttributeMaxDynamicSharedMemorySize, SMEM_SZ);

    // V-job distribution: fill each phase launch to its ceil boundary
    int nsm = 148;
    cudaDeviceGetAttribute(&nsm, cudaDevAttrMultiProcessorCount, 0);
    const int slots = 2 * nsm;
    auto cap = [slots](int jobs) { return ((jobs + slots - 1) / slots) * slots - jobs; };
    int rem = 512;
    int v1 = rem < (slots - 64) ? rem : (slots - 64); rem -= v1;
    int v2 = rem < cap(512)  ? rem : cap(512);        rem -= v2;
    int v3 = rem < cap(1024) ? rem : cap(1024);       rem -= v3;
    v3 += rem;   // leftover (accepts +1 wave on the largest launch)

    const long SD = (long)S_LEN * D_DIM, SS = (long)S_LEN * S_LEN;

    // ---- fused data prep (x split + all weight digits) ----
    prep_all<<<8192 + 3 * 1024, 256>>>(x, Wq, Wk, Wv,
        (bf16*)xh, (bf16*)xl, (bf16*)wqh, (bf16*)wql,
        (bf16*)wkh, (bf16*)wkl, (bf16*)wvth, (bf16*)wvtl);

    // ---- L1: M' (64) + V filler ----
    gemm_mix<1><<<64 + v1, 128, SMEM_SZ>>>(
        (bf16*)xh, (bf16*)xl, (bf16*)wqh, (bf16*)wql, (bf16*)wkh, (bf16*)wkl,
        (bf16*)wvth, (bf16*)wvtl, (bf16*)mh, (bf16*)ml, (bf16*)th, (bf16*)tl,
        (bf16*)vth, (bf16*)vtl, (bf16*)mh, (bf16*)ml, (bf16*)th, (bf16*)tl,
        (float*)sc, 64, 0);

    // ---- L2: T (512) + V filler ----
    gemm_mix<2><<<512 + v2, 128, SMEM_SZ>>>(
        (bf16*)xh, (bf16*)xl, (bf16*)wqh, (bf16*)wql, (bf16*)wkh, (bf16*)wkl,
        (bf16*)wvth, (bf16*)wvtl, (bf16*)mh, (bf16*)ml, (bf16*)th, (bf16*)tl,
        (bf16*)vth, (bf16*)vtl, (bf16*)mh, (bf16*)ml, (bf16*)th, (bf16*)tl,
        (float*)sc, 512, v1);

    // ---- L3: scores (1024) + V filler ----
    gemm_mix<3><<<1024 + v3, 128, SMEM_SZ>>>(
        (bf16*)xh, (bf16*)xl, (bf16*)wqh, (bf16*)wql, (bf16*)wkh, (bf16*)wkl,
        (bf16*)wvth, (bf16*)wvtl, (bf16*)mh, (bf16*)ml, (bf16*)th, (bf16*)tl,
        (bf16*)vth, (bf16*)vtl, (bf16*)mh, (bf16*)ml, (bf16*)th, (bf16*)tl,
        (float*)sc, 1024, v1 + v2);

    softmax_rows<<<MTOT / 8, 256>>>((const float*)sc, (bf16*)wh, (bf16*)wl);

    // ---- AV: out = softmaxW * V ----
    gemm_b<<<dim3(D_DIM / 128, S_LEN / 128, BATCH), 128, SMEM_SZ>>>(
        (bf16*)wh, (bf16*)wl, (bf16*)vth, (bf16*)vtl,
        out, D_DIM, S_LEN, SS, SD, SD);
}